// round 10
// baseline (speedup 1.0000x reference)
#include <cuda_runtime.h>

#define BN   16
#define CN   80
#define HN   128
#define WN   128
#define HWN  (HN*WN)
#define NPLANES (BN*CN)
#define TOPK 100
#define NB1  2048
#define SBUF 3072                   // shared candidate cap per plane (expected ~1820)
#define GCAP 1024                   // compacted per-plane global cap (expected ~130)
#define SCAP 2048                   // per-batch survivor cap (expected ~700)
#define RCAP 1024                   // refined cap (expected ~101)
#define FULLM 0xffffffffu
#define NEG_INF __int_as_float(0xff800000)

// ---- scratch (device globals; allocation-free contract) ----
__device__ unsigned long long g_cand[NPLANES][GCAP];  // compacted plane top-~100+
__device__ int g_pcnt[NPLANES];                       // written unconditionally
__device__ int g_done[BN];                            // ticket; consumer-reset each run

__device__ __forceinline__ int bin1f(float v){
    int b = (int)(v * 2048.0f);
    return b < 0 ? 0 : (b > NB1-1 ? NB1-1 : b);
}
__device__ __forceinline__ int bin2f(float v, int b1){
    float f = v * 2048.0f - (float)b1;
    int b = (int)(f * 2048.0f);
    return b < 0 ? 0 : (b > NB1-1 ? NB1-1 : b);
}

// Warp-serial suffix cut scan from the top: largest bin with initAcc+suffix>=TOPK.
__device__ __forceinline__ int cut_scan(const int* histArr, int initAcc, int lane){
    int acc = initAcc, cut = 0;
    for (int bb = NB1 - 32; bb >= 0; bb -= 32){
        int suf = histArr[bb + lane];
        #pragma unroll
        for (int off = 1; off < 32; off <<= 1){
            int t = __shfl_down_sync(FULLM, suf, off);
            if (lane + off < 32) suf += t;
        }
        unsigned bal = __ballot_sync(FULLM, acc + suf >= TOPK);
        if (bal){ cut = bb + (31 - __clz(bal)); break; }
        acc += __shfl_sync(FULLM, suf, 0);
    }
    return cut;
}

// Horizontal 3-max of a row held as float4-per-lane (32 lanes cover 128 cols).
__device__ __forceinline__ float4 hmax4(float4 v, int lane){
    float left  = __shfl_up_sync(FULLM, v.w, 1);
    float right = __shfl_down_sync(FULLM, v.x, 1);
    left  = (lane == 0)  ? NEG_INF : left;
    right = (lane == 31) ? NEG_INF : right;
    float4 h;
    h.x = fmaxf(fmaxf(left, v.x), v.y);
    h.y = fmaxf(fmaxf(v.x, v.y), v.z);
    h.z = fmaxf(fmaxf(v.y, v.z), v.w);
    h.w = fmaxf(fmaxf(v.z, v.w), right);
    return h;
}

// Emit keeps: 4 ballots + ONE warp atomic + STS per row (no divergent atomics).
__device__ __forceinline__ void emit_row(float4 v, float4 hp, float4 hc, float4 hn,
                                         int r, int lane, unsigned lmask, int ch,
                                         int* scnt, unsigned long long* sbuf){
    float wm0 = fmaxf(fmaxf(hp.x, hc.x), hn.x);
    float wm1 = fmaxf(fmaxf(hp.y, hc.y), hn.y);
    float wm2 = fmaxf(fmaxf(hp.z, hc.z), hn.z);
    float wm3 = fmaxf(fmaxf(hp.w, hc.w), hn.w);
    bool k0 = (v.x == wm0), k1 = (v.y == wm1), k2 = (v.z == wm2), k3 = (v.w == wm3);
    unsigned b0 = __ballot_sync(FULLM, k0);
    unsigned b1 = __ballot_sync(FULLM, k1);
    unsigned b2 = __ballot_sync(FULLM, k2);
    unsigned b3 = __ballot_sync(FULLM, k3);
    if (b0 | b1 | b2 | b3){                            // warp-uniform branch
        int c0 = __popc(b0), c1 = __popc(b1), c2 = __popc(b2);
        int total = c0 + c1 + c2 + __popc(b3);
        int base = 0;
        if (lane == 0) base = atomicAdd(scnt, total);
        base = __shfl_sync(FULLM, base, 0);
        const unsigned ib = (unsigned)(ch*HWN + r*WN + lane*4);
        if (k0){ int p = base + __popc(b0 & lmask);
                 if (p < SBUF) sbuf[p] = ((unsigned long long)__float_as_uint(v.x) << 32) | (unsigned)(~ib); }
        if (k1){ int p = base + c0 + __popc(b1 & lmask);
                 if (p < SBUF) sbuf[p] = ((unsigned long long)__float_as_uint(v.y) << 32) | (unsigned)(~(ib+1)); }
        if (k2){ int p = base + c0 + c1 + __popc(b2 & lmask);
                 if (p < SBUF) sbuf[p] = ((unsigned long long)__float_as_uint(v.z) << 32) | (unsigned)(~(ib+2)); }
        if (k3){ int p = base + c0 + c1 + c2 + __popc(b3 & lmask);
                 if (p < SBUF) sbuf[p] = ((unsigned long long)__float_as_uint(v.w) << 32) | (unsigned)(~(ib+3)); }
    }
}

// Fused kernel: per-plane NMS + plane cut + compaction; the LAST plane-block
// of each batch runs the selection tail (hist -> b1 -> compact -> refine ->
// rank ~101 -> decode) while other batches' blocks still run NMS.
__global__ __launch_bounds__(256, 6) void fused_kernel(const float* __restrict__ hm,
                                                       const float* __restrict__ offset,
                                                       const float* __restrict__ wh,
                                                       float* __restrict__ out){
    __shared__ unsigned long long sbuf[SBUF];   // also reused as sv / sv2
    __shared__ int shist[NB1];                  // both histogram levels
    __shared__ int spcnt[CN];
    __shared__ int scnt, scnt2, sCut, sLast, sCol, sCol2, sCntHi, sB2;
    const int plane = blockIdx.x;
    const int b  = plane / CN;
    const int ch = plane % CN;
    const int wid  = threadIdx.x >> 5;
    const int lane = threadIdx.x & 31;
    const unsigned lmask = (1u << lane) - 1u;
    const int r0 = wid * 16;
    const float* base = hm + (size_t)plane * HWN + lane*4;

    if (threadIdx.x == 0){ scnt = 0; scnt2 = 0; sCut = 0; }
    for (int i = threadIdx.x; i < NB1; i += 256) shist[i] = 0;
    __syncthreads();

    // ---- NMS: register-rolling separable 3x3 max ----
    float4 v_cur, v_next, h_prev, h_cur, h_next;
    if (r0 > 0){
        h_prev = hmax4(*(const float4*)(base + (size_t)(r0-1)*WN), lane);
    } else {
        h_prev = make_float4(NEG_INF, NEG_INF, NEG_INF, NEG_INF);
    }
    v_cur = *(const float4*)(base + (size_t)r0*WN);
    h_cur = hmax4(v_cur, lane);

    #pragma unroll 3
    for (int r = r0; r < r0 + 15; ++r){
        v_next = *(const float4*)(base + (size_t)(r+1)*WN);
        h_next = hmax4(v_next, lane);
        emit_row(v_cur, h_prev, h_cur, h_next, r, lane, lmask, ch, &scnt, sbuf);
        h_prev = h_cur; h_cur = h_next; v_cur = v_next;
    }
    if (r0 + 16 < HN){
        h_next = hmax4(*(const float4*)(base + (size_t)(r0+16)*WN), lane);
    } else {
        h_next = make_float4(NEG_INF, NEG_INF, NEG_INF, NEG_INF);
    }
    emit_row(v_cur, h_prev, h_cur, h_next, r0+15, lane, lmask, ch, &scnt, sbuf);

    // ---- per-plane histogram -> plane cut -> compact to global ----
    __syncthreads();
    const int nc = (scnt > SBUF) ? SBUF : scnt;
    for (int i = threadIdx.x; i < nc; i += 256){
        float v = __uint_as_float((unsigned)(sbuf[i] >> 32));
        atomicAdd(&shist[bin1f(v)], 1);
    }
    __syncthreads();
    if (wid == 0){
        int cut = cut_scan(shist, 0, lane);
        if (lane == 0) sCut = cut;
    }
    __syncthreads();
    const int p1 = sCut;

    unsigned long long* dst = g_cand[plane];
    for (int i0 = 0; i0 < nc; i0 += 256){
        const int i = i0 + threadIdx.x;
        const bool valid = (i < nc);
        unsigned long long kk = valid ? sbuf[i] : 0ull;
        int bin = bin1f(__uint_as_float((unsigned)(kk >> 32)));
        bool take = valid && (bin >= p1);
        unsigned bal = __ballot_sync(FULLM, take);
        int wb = 0;
        if (lane == 0 && bal) wb = atomicAdd(&scnt2, __popc(bal));
        wb = __shfl_sync(FULLM, wb, 0);
        if (take){
            int pos = wb + __popc(bal & lmask);
            if (pos < GCAP) dst[pos] = kk;
        }
    }
    __syncthreads();
    if (threadIdx.x == 0) g_pcnt[plane] = (scnt2 > GCAP) ? GCAP : scnt2;

    // ---- ticket: last plane-block of this batch runs the selection tail ----
    __threadfence();
    __syncthreads();
    if (threadIdx.x == 0) sLast = (atomicAdd(&g_done[b], 1) == CN - 1);
    __syncthreads();
    if (!sLast) return;
    __threadfence();                              // acquire side
    if (threadIdx.x == 0){
        g_done[b] = 0;                            // consumer reset for next replay
        sCol = 0; sCol2 = 0; sCntHi = 0; sB2 = 0; sCut = 0;
    }
    for (int i = threadIdx.x; i < NB1; i += 256) shist[i] = 0;
    if (threadIdx.x < CN) spcnt[threadIdx.x] = g_pcnt[b*CN + threadIdx.x];
    __syncthreads();

    // Pass A: level-1 histogram over the batch's ~10k compacted candidates
    for (int p = wid; p < CN; p += 8){
        const int cnt = spcnt[p];
        const unsigned long long* src = g_cand[b*CN + p];
        for (int i = lane; i < cnt; i += 32){
            float v = __uint_as_float((unsigned)(src[i] >> 32));
            atomicAdd(&shist[bin1f(v)], 1);
        }
    }
    __syncthreads();
    if (wid == 0){
        int cut = cut_scan(shist, 0, lane);
        if (lane == 0) sCut = cut;
    }
    __syncthreads();
    const int b1 = sCut;

    // Pass B: compact survivors (bin >= b1) into shared sv (reuse sbuf)
    unsigned long long* sv = sbuf;
    for (int p = wid; p < CN; p += 8){
        const int cnt = spcnt[p];
        const unsigned long long* src = g_cand[b*CN + p];
        for (int i0 = 0; i0 < cnt; i0 += 32){
            const int i = i0 + lane;
            const bool valid = (i < cnt);
            unsigned long long kk = valid ? src[i] : 0ull;
            float v = __uint_as_float((unsigned)(kk >> 32));
            bool take = valid && (bin1f(v) >= b1);
            unsigned bal = __ballot_sync(FULLM, take);
            int wb = 0;
            if (lane == 0 && bal) wb = atomicAdd(&sCol, __popc(bal));
            wb = __shfl_sync(FULLM, wb, 0);
            if (take){
                int pos = wb + __popc(bal & lmask);
                if (pos < SCAP) sv[pos] = kk;
            }
        }
    }
    __syncthreads();
    const int m = (sCol > SCAP) ? SCAP : sCol;

    // Level-2: sub-bin histogram of the bin==b1 items
    for (int i = threadIdx.x; i < NB1; i += 256) shist[i] = 0;
    __syncthreads();
    for (int i = threadIdx.x; i < m; i += 256){
        float v = __uint_as_float((unsigned)(sv[i] >> 32));
        if (bin1f(v) > b1) atomicAdd(&sCntHi, 1);
        else atomicAdd(&shist[bin2f(v, b1)], 1);
    }
    __syncthreads();
    if (wid == 0){
        int cut = cut_scan(shist, sCntHi, lane);
        if (lane == 0) sB2 = cut;
    }
    __syncthreads();
    const int b2 = sB2;

    // Compact refined set (~101). Ranks within it equal global ranks.
    unsigned long long* sv2 = sbuf + SCAP;        // disjoint from sv[0..SCAP)
    for (int i0 = 0; i0 < m; i0 += 256){
        const int i = i0 + threadIdx.x;
        const bool valid = (i < m);
        unsigned long long kk = valid ? sv[i] : 0ull;
        float v = __uint_as_float((unsigned)(kk >> 32));
        bool take = valid && ((bin1f(v) > b1) || (bin2f(v, b1) >= b2));
        unsigned bal = __ballot_sync(FULLM, take);
        int wb = 0;
        if (lane == 0 && bal) wb = atomicAdd(&sCol2, __popc(bal));
        wb = __shfl_sync(FULLM, wb, 0);
        if (take){
            int pos = wb + __popc(bal & lmask);
            if (pos < SBUF - SCAP) sv2[pos] = kk;
        }
    }
    __syncthreads();
    int m2 = sCol2; if (m2 > SBUF - SCAP) m2 = SBUF - SCAP;

    for (int e = threadIdx.x; e < m2; e += 256){
        unsigned long long key = sv2[e];
        int rank = 0;
        for (int j = 0; j < m2; ++j) rank += (sv2[j] > key);
        if (rank < TOPK){
            unsigned vb = (unsigned)(key >> 32);
            int idx = (int)(~(unsigned)key);
            float score = __uint_as_float(vb);
            int chn = idx / HWN;
            int spatial = idx - chn*HWN;
            int ys = spatial >> 7, xs = spatial & (WN-1);
            const float* offb = offset + (size_t)b * 2 * HWN;
            const float* whb  = wh     + (size_t)b * 2 * HWN;
            float ox = offb[spatial], oy = offb[HWN + spatial];
            float ww = whb[spatial],  hh = whb[HWN + spatial];
            float cx = (float)xs + ox, cy = (float)ys + oy;
            float hw2 = ww * 0.5f, hh2 = hh * 0.5f;

            float* out_ids = out;                 // (B,100,1)
            float* out_sc  = out + BN*TOPK;       // (B,100,1)
            float* out_bb  = out + 2*BN*TOPK;     // (B,100,4)
            out_ids[b*TOPK + rank] = (float)chn;
            out_sc [b*TOPK + rank] = score;
            float* bbp = out_bb + (size_t)(b*TOPK + rank)*4;
            bbp[0] = (cx - hw2)*4.0f;
            bbp[1] = (cy - hh2)*4.0f;
            bbp[2] = (cx + hw2)*4.0f;
            bbp[3] = (cy + hh2)*4.0f;
        }
    }
}

extern "C" void kernel_launch(void* const* d_in, const int* in_sizes, int n_in,
                              void* d_out, int out_size){
    const float* hm     = (const float*)d_in[0];
    const float* offset = (const float*)d_in[1];
    const float* wh     = (const float*)d_in[2];
    float* out = (float*)d_out;

    fused_kernel<<<NPLANES, 256>>>(hm, offset, wh, out);
}

// round 12
// speedup vs baseline: 1.3652x; 1.3652x over previous
#include <cuda_runtime.h>

#define BN   16
#define CN   80
#define HN   128
#define WN   128
#define HWN  (HN*WN)
#define NPLANES (BN*CN)
#define TOPK 100
#define NB1  2048
#define SBUF 2560                   // shared candidate cap per plane (expected ~1820)
#define SCMP 1024                   // staging cap for plane survivors (expected ~130)
#define BCAP2 16384                 // per-batch contiguous candidate cap (expected ~10.4k)
#define SCAP 2048                   // per-batch survivor cap (expected ~700)
#define RCAP 1024                   // refined cap (expected ~101)
#define FULLM 0xffffffffu
#define NEG_INF __int_as_float(0xff800000)

// ---- scratch (device globals; allocation-free contract) ----
__device__ unsigned long long g_bcand[BN][BCAP2]; // contiguous per-batch candidates
__device__ int g_bcnt[BN];                        // zero at load; consumer-reset by K2

__device__ __forceinline__ int bin1f(float v){
    int b = (int)(v * 2048.0f);
    return b < 0 ? 0 : (b > NB1-1 ? NB1-1 : b);
}
__device__ __forceinline__ int bin2f(float v, int b1){
    float f = v * 2048.0f - (float)b1;
    int b = (int)(f * 2048.0f);
    return b < 0 ? 0 : (b > NB1-1 ? NB1-1 : b);
}

// Warp-serial suffix cut scan from the top: largest bin with initAcc+suffix>=TOPK.
__device__ __forceinline__ int cut_scan(const int* histArr, int initAcc, int lane){
    int acc = initAcc, cut = 0;
    for (int bb = NB1 - 32; bb >= 0; bb -= 32){
        int suf = histArr[bb + lane];
        #pragma unroll
        for (int off = 1; off < 32; off <<= 1){
            int t = __shfl_down_sync(FULLM, suf, off);
            if (lane + off < 32) suf += t;
        }
        unsigned bal = __ballot_sync(FULLM, acc + suf >= TOPK);
        if (bal){ cut = bb + (31 - __clz(bal)); break; }
        acc += __shfl_sync(FULLM, suf, 0);
    }
    return cut;
}

// Horizontal 3-max of a row held as float4-per-lane (32 lanes cover 128 cols).
__device__ __forceinline__ float4 hmax4(float4 v, int lane){
    float left  = __shfl_up_sync(FULLM, v.w, 1);
    float right = __shfl_down_sync(FULLM, v.x, 1);
    left  = (lane == 0)  ? NEG_INF : left;
    right = (lane == 31) ? NEG_INF : right;
    float4 h;
    h.x = fmaxf(fmaxf(left, v.x), v.y);
    h.y = fmaxf(fmaxf(v.x, v.y), v.z);
    h.z = fmaxf(fmaxf(v.y, v.z), v.w);
    h.w = fmaxf(fmaxf(v.z, v.w), right);
    return h;
}

// Emit keeps: 4 ballots + ONE warp atomic + STS per row (no divergent atomics).
__device__ __forceinline__ void emit_row(float4 v, float4 hp, float4 hc, float4 hn,
                                         int r, int lane, unsigned lmask, int ch,
                                         int* scnt, unsigned long long* sbuf){
    float wm0 = fmaxf(fmaxf(hp.x, hc.x), hn.x);
    float wm1 = fmaxf(fmaxf(hp.y, hc.y), hn.y);
    float wm2 = fmaxf(fmaxf(hp.z, hc.z), hn.z);
    float wm3 = fmaxf(fmaxf(hp.w, hc.w), hn.w);
    bool k0 = (v.x == wm0), k1 = (v.y == wm1), k2 = (v.z == wm2), k3 = (v.w == wm3);
    unsigned b0 = __ballot_sync(FULLM, k0);
    unsigned b1 = __ballot_sync(FULLM, k1);
    unsigned b2 = __ballot_sync(FULLM, k2);
    unsigned b3 = __ballot_sync(FULLM, k3);
    if (b0 | b1 | b2 | b3){                            // warp-uniform branch
        int c0 = __popc(b0), c1 = __popc(b1), c2 = __popc(b2);
        int total = c0 + c1 + c2 + __popc(b3);
        int base = 0;
        if (lane == 0) base = atomicAdd(scnt, total);
        base = __shfl_sync(FULLM, base, 0);
        const unsigned ib = (unsigned)(ch*HWN + r*WN + lane*4);
        if (k0){ int p = base + __popc(b0 & lmask);
                 if (p < SBUF) sbuf[p] = ((unsigned long long)__float_as_uint(v.x) << 32) | (unsigned)(~ib); }
        if (k1){ int p = base + c0 + __popc(b1 & lmask);
                 if (p < SBUF) sbuf[p] = ((unsigned long long)__float_as_uint(v.y) << 32) | (unsigned)(~(ib+1)); }
        if (k2){ int p = base + c0 + c1 + __popc(b2 & lmask);
                 if (p < SBUF) sbuf[p] = ((unsigned long long)__float_as_uint(v.z) << 32) | (unsigned)(~(ib+2)); }
        if (k3){ int p = base + c0 + c1 + c2 + __popc(b3 & lmask);
                 if (p < SBUF) sbuf[p] = ((unsigned long long)__float_as_uint(v.w) << 32) | (unsigned)(~(ib+3)); }
    }
}

// K1: 3x3 NMS + per-plane top-100 cut; survivors staged in shared, then ONE
// block-level atomic reserves a slice of the per-batch contiguous array.
__global__ __launch_bounds__(256) void nms_kernel(const float* __restrict__ hm){
    __shared__ unsigned long long sbuf[SBUF];
    __shared__ unsigned long long sstage[SCMP];
    __shared__ int shist[NB1];
    __shared__ int scnt, scnt2, sCut, sBase;
    const int plane = blockIdx.x;
    const int b  = plane / CN;
    const int ch = plane % CN;
    const int wid  = threadIdx.x >> 5;
    const int lane = threadIdx.x & 31;
    const unsigned lmask = (1u << lane) - 1u;
    const int r0 = wid * 16;
    const float* base = hm + (size_t)plane * HWN + lane*4;

    if (threadIdx.x == 0){ scnt = 0; scnt2 = 0; sCut = 0; }
    for (int i = threadIdx.x; i < NB1; i += 256) shist[i] = 0;
    __syncthreads();

    // ---- NMS: register-rolling separable 3x3 max ----
    float4 v_cur, v_next, h_prev, h_cur, h_next;
    if (r0 > 0){
        h_prev = hmax4(*(const float4*)(base + (size_t)(r0-1)*WN), lane);
    } else {
        h_prev = make_float4(NEG_INF, NEG_INF, NEG_INF, NEG_INF);
    }
    v_cur = *(const float4*)(base + (size_t)r0*WN);
    h_cur = hmax4(v_cur, lane);

    #pragma unroll 3
    for (int r = r0; r < r0 + 15; ++r){
        v_next = *(const float4*)(base + (size_t)(r+1)*WN);
        h_next = hmax4(v_next, lane);
        emit_row(v_cur, h_prev, h_cur, h_next, r, lane, lmask, ch, &scnt, sbuf);
        h_prev = h_cur; h_cur = h_next; v_cur = v_next;
    }
    if (r0 + 16 < HN){
        h_next = hmax4(*(const float4*)(base + (size_t)(r0+16)*WN), lane);
    } else {
        h_next = make_float4(NEG_INF, NEG_INF, NEG_INF, NEG_INF);
    }
    emit_row(v_cur, h_prev, h_cur, h_next, r0+15, lane, lmask, ch, &scnt, sbuf);

    // ---- per-plane histogram -> plane cut ----
    __syncthreads();
    const int nc = (scnt > SBUF) ? SBUF : scnt;
    for (int i = threadIdx.x; i < nc; i += 256){
        float v = __uint_as_float((unsigned)(sbuf[i] >> 32));
        atomicAdd(&shist[bin1f(v)], 1);
    }
    __syncthreads();
    if (wid == 0){
        int cut = cut_scan(shist, 0, lane);
        if (lane == 0) sCut = cut;
    }
    __syncthreads();
    const int p1 = sCut;

    // ---- compact plane survivors (bin >= p1) into shared staging ----
    for (int i0 = 0; i0 < nc; i0 += 256){
        const int i = i0 + threadIdx.x;
        const bool valid = (i < nc);
        unsigned long long kk = valid ? sbuf[i] : 0ull;
        int bin = bin1f(__uint_as_float((unsigned)(kk >> 32)));
        bool take = valid && (bin >= p1);
        unsigned bal = __ballot_sync(FULLM, take);
        int wb = 0;
        if (lane == 0 && bal) wb = atomicAdd(&scnt2, __popc(bal));
        wb = __shfl_sync(FULLM, wb, 0);
        if (take){
            int pos = wb + __popc(bal & lmask);
            if (pos < SCMP) sstage[pos] = kk;
        }
    }
    __syncthreads();
    const int total = (scnt2 > SCMP) ? SCMP : scnt2;
    if (threadIdx.x == 0) sBase = atomicAdd(&g_bcnt[b], total);
    __syncthreads();
    const int gbase = sBase;
    for (int i = threadIdx.x; i < total; i += 256){
        int gp = gbase + i;
        if (gp < BCAP2) g_bcand[b][gp] = sstage[i];
    }
}

// K2: one block per batch over a CONTIGUOUS candidate list.
// Level-1 hist -> cut b1 -> compact to shared -> level-2 refine -> rank -> decode.
__global__ __launch_bounds__(1024) void filter_rank_kernel(const float* __restrict__ offset,
                                                           const float* __restrict__ wh,
                                                           float* __restrict__ out){
    __shared__ int hist[NB1];
    __shared__ unsigned long long sv[SCAP];
    __shared__ unsigned long long sv2[RCAP];
    __shared__ int sB1, sB2, sCol, sCol2, sCntHi;
    const int b    = blockIdx.x;
    const int tid  = threadIdx.x;
    const int wid  = tid >> 5;
    const int lane = tid & 31;
    const unsigned lmask = (1u << lane) - 1u;

    if (tid == 0){ sB1 = 0; sB2 = 0; sCol = 0; sCol2 = 0; sCntHi = 0; }
    for (int i = tid; i < NB1; i += 1024) hist[i] = 0;
    int cnt = g_bcnt[b]; if (cnt > BCAP2) cnt = BCAP2;
    const unsigned long long* src = g_bcand[b];
    __syncthreads();

    // Pass A: level-1 histogram, coalesced stride-1024 loads (high MLP)
    for (int i = tid; i < cnt; i += 1024){
        float v = __uint_as_float((unsigned)(src[i] >> 32));
        atomicAdd(&hist[bin1f(v)], 1);
    }
    __syncthreads();
    if (wid == 0){
        int cut = cut_scan(hist, 0, lane);
        if (lane == 0) sB1 = cut;
    }
    __syncthreads();
    const int b1 = sB1;

    // Pass B: compact survivors (bin >= b1); data now L1/L2-hot
    for (int i0 = 0; i0 < cnt; i0 += 1024){
        const int i = i0 + tid;
        const bool valid = (i < cnt);
        unsigned long long kk = valid ? src[i] : 0ull;
        float v = __uint_as_float((unsigned)(kk >> 32));
        bool take = valid && (bin1f(v) >= b1);
        unsigned bal = __ballot_sync(FULLM, take);
        int wb = 0;
        if (lane == 0 && bal) wb = atomicAdd(&sCol, __popc(bal));
        wb = __shfl_sync(FULLM, wb, 0);
        if (take){
            int pos = wb + __popc(bal & lmask);
            if (pos < SCAP) sv[pos] = kk;
        }
    }
    __syncthreads();
    const int m = (sCol > SCAP) ? SCAP : sCol;

    // Level-2: sub-bin histogram of the bin==b1 items
    for (int i = tid; i < NB1; i += 1024) hist[i] = 0;
    __syncthreads();
    for (int i = tid; i < m; i += 1024){
        float v = __uint_as_float((unsigned)(sv[i] >> 32));
        if (bin1f(v) > b1) atomicAdd(&sCntHi, 1);
        else atomicAdd(&hist[bin2f(v, b1)], 1);
    }
    __syncthreads();
    if (wid == 0){
        int cut = cut_scan(hist, sCntHi, lane);
        if (lane == 0) sB2 = cut;
    }
    __syncthreads();
    const int b2 = sB2;

    // Compact refined set (~101 items). Ranks within it equal global ranks.
    for (int i0 = 0; i0 < m; i0 += 1024){
        const int i = i0 + tid;
        const bool valid = (i < m);
        unsigned long long kk = valid ? sv[i] : 0ull;
        float v = __uint_as_float((unsigned)(kk >> 32));
        bool take = valid && ((bin1f(v) > b1) || (bin2f(v, b1) >= b2));
        unsigned bal = __ballot_sync(FULLM, take);
        int wb = 0;
        if (lane == 0 && bal) wb = atomicAdd(&sCol2, __popc(bal));
        wb = __shfl_sync(FULLM, wb, 0);
        if (take){
            int pos = wb + __popc(bal & lmask);
            if (pos < RCAP) sv2[pos] = kk;
        }
    }
    __syncthreads();
    const int m2 = (sCol2 > RCAP) ? RCAP : sCol2;

    for (int e = tid; e < m2; e += 1024){
        unsigned long long key = sv2[e];
        int rank = 0;
        for (int j = 0; j < m2; ++j) rank += (sv2[j] > key);
        if (rank < TOPK){
            unsigned vb = (unsigned)(key >> 32);
            int idx = (int)(~(unsigned)key);
            float score = __uint_as_float(vb);
            int chn = idx / HWN;
            int spatial = idx - chn*HWN;
            int ys = spatial >> 7, xs = spatial & (WN-1);
            const float* offb = offset + (size_t)b * 2 * HWN;
            const float* whb  = wh     + (size_t)b * 2 * HWN;
            float ox = offb[spatial], oy = offb[HWN + spatial];
            float ww = whb[spatial],  hh = whb[HWN + spatial];
            float cx = (float)xs + ox, cy = (float)ys + oy;
            float hw2 = ww * 0.5f, hh2 = hh * 0.5f;

            float* out_ids = out;                 // (B,100,1)
            float* out_sc  = out + BN*TOPK;       // (B,100,1)
            float* out_bb  = out + 2*BN*TOPK;     // (B,100,4)
            out_ids[b*TOPK + rank] = (float)chn;
            out_sc [b*TOPK + rank] = score;
            float* bbp = out_bb + (size_t)(b*TOPK + rank)*4;
            bbp[0] = (cx - hw2)*4.0f;
            bbp[1] = (cy - hh2)*4.0f;
            bbp[2] = (cx + hw2)*4.0f;
            bbp[3] = (cy + hh2)*4.0f;
        }
    }

    // consumer reset so the next replay starts from a clean counter
    __syncthreads();
    if (tid == 0) g_bcnt[b] = 0;
}

extern "C" void kernel_launch(void* const* d_in, const int* in_sizes, int n_in,
                              void* d_out, int out_size){
    const float* hm     = (const float*)d_in[0];
    const float* offset = (const float*)d_in[1];
    const float* wh     = (const float*)d_in[2];
    float* out = (float*)d_out;

    nms_kernel<<<NPLANES, 256>>>(hm);
    filter_rank_kernel<<<BN, 1024>>>(offset, wh, out);
}

// round 13
// speedup vs baseline: 1.4678x; 1.0752x over previous
#include <cuda_runtime.h>

#define BN   16
#define CN   80
#define HN   128
#define WN   128
#define HWN  (HN*WN)
#define NPLANES (BN*CN)
#define TOPK 100
#define NB1  2048
#define SBUF 2560                   // shared candidate cap per plane (expected ~1820)
#define SCMP 1024                   // staging cap for plane survivors (expected ~130)
#define BCAP2 16384                 // per-batch contiguous candidate cap (expected ~10.4k)
#define SCAP 2048                   // per-batch survivor cap (expected ~700)
#define RCAP 1024                   // refined cap (expected ~101)
#define FULLM 0xffffffffu
#define NEG_INF __int_as_float(0xff800000)

// ---- scratch (device globals; allocation-free contract) ----
__device__ unsigned long long g_bcand[BN][BCAP2]; // contiguous per-batch candidates
__device__ int g_bcnt[BN];                        // zero at load; consumer-reset by K2
__device__ int g_hist[BN][NB1];                   // zero at load; consumer-reset by K2

__device__ __forceinline__ int bin1f(float v){
    int b = (int)(v * 2048.0f);
    return b < 0 ? 0 : (b > NB1-1 ? NB1-1 : b);
}
__device__ __forceinline__ int bin2f(float v, int b1){
    float f = v * 2048.0f - (float)b1;
    int b = (int)(f * 2048.0f);
    return b < 0 ? 0 : (b > NB1-1 ? NB1-1 : b);
}

// Warp-serial suffix cut scan from the top: largest bin with initAcc+suffix>=TOPK.
__device__ __forceinline__ int cut_scan(const int* histArr, int initAcc, int lane){
    int acc = initAcc, cut = 0;
    for (int bb = NB1 - 32; bb >= 0; bb -= 32){
        int suf = histArr[bb + lane];
        #pragma unroll
        for (int off = 1; off < 32; off <<= 1){
            int t = __shfl_down_sync(FULLM, suf, off);
            if (lane + off < 32) suf += t;
        }
        unsigned bal = __ballot_sync(FULLM, acc + suf >= TOPK);
        if (bal){ cut = bb + (31 - __clz(bal)); break; }
        acc += __shfl_sync(FULLM, suf, 0);
    }
    return cut;
}

// Horizontal 3-max of a row held as float4-per-lane (32 lanes cover 128 cols).
__device__ __forceinline__ float4 hmax4(float4 v, int lane){
    float left  = __shfl_up_sync(FULLM, v.w, 1);
    float right = __shfl_down_sync(FULLM, v.x, 1);
    left  = (lane == 0)  ? NEG_INF : left;
    right = (lane == 31) ? NEG_INF : right;
    float4 h;
    h.x = fmaxf(fmaxf(left, v.x), v.y);
    h.y = fmaxf(fmaxf(v.x, v.y), v.z);
    h.z = fmaxf(fmaxf(v.y, v.z), v.w);
    h.w = fmaxf(fmaxf(v.z, v.w), right);
    return h;
}

// Emit keeps: 4 ballots + ONE warp atomic + STS per row (no divergent atomics).
__device__ __forceinline__ void emit_row(float4 v, float4 hp, float4 hc, float4 hn,
                                         int r, int lane, unsigned lmask, int ch,
                                         int* scnt, unsigned long long* sbuf){
    float wm0 = fmaxf(fmaxf(hp.x, hc.x), hn.x);
    float wm1 = fmaxf(fmaxf(hp.y, hc.y), hn.y);
    float wm2 = fmaxf(fmaxf(hp.z, hc.z), hn.z);
    float wm3 = fmaxf(fmaxf(hp.w, hc.w), hn.w);
    bool k0 = (v.x == wm0), k1 = (v.y == wm1), k2 = (v.z == wm2), k3 = (v.w == wm3);
    unsigned b0 = __ballot_sync(FULLM, k0);
    unsigned b1 = __ballot_sync(FULLM, k1);
    unsigned b2 = __ballot_sync(FULLM, k2);
    unsigned b3 = __ballot_sync(FULLM, k3);
    if (b0 | b1 | b2 | b3){                            // warp-uniform branch
        int c0 = __popc(b0), c1 = __popc(b1), c2 = __popc(b2);
        int total = c0 + c1 + c2 + __popc(b3);
        int base = 0;
        if (lane == 0) base = atomicAdd(scnt, total);
        base = __shfl_sync(FULLM, base, 0);
        const unsigned ib = (unsigned)(ch*HWN + r*WN + lane*4);
        if (k0){ int p = base + __popc(b0 & lmask);
                 if (p < SBUF) sbuf[p] = ((unsigned long long)__float_as_uint(v.x) << 32) | (unsigned)(~ib); }
        if (k1){ int p = base + c0 + __popc(b1 & lmask);
                 if (p < SBUF) sbuf[p] = ((unsigned long long)__float_as_uint(v.y) << 32) | (unsigned)(~(ib+1)); }
        if (k2){ int p = base + c0 + c1 + __popc(b2 & lmask);
                 if (p < SBUF) sbuf[p] = ((unsigned long long)__float_as_uint(v.z) << 32) | (unsigned)(~(ib+2)); }
        if (k3){ int p = base + c0 + c1 + c2 + __popc(b3 & lmask);
                 if (p < SBUF) sbuf[p] = ((unsigned long long)__float_as_uint(v.w) << 32) | (unsigned)(~(ib+3)); }
    }
}

// K1: 3x3 NMS + per-plane top-100 cut; survivors staged in shared, then ONE
// block atomic reserves a slice of the per-batch contiguous array; each written
// survivor is also REDG-counted into the per-batch level-1 histogram.
__global__ __launch_bounds__(256) void nms_kernel(const float* __restrict__ hm){
    __shared__ unsigned long long sbuf[SBUF];
    __shared__ unsigned long long sstage[SCMP];
    __shared__ int shist[NB1];
    __shared__ int scnt, scnt2, sCut, sBase;
    const int plane = blockIdx.x;
    const int b  = plane / CN;
    const int ch = plane % CN;
    const int wid  = threadIdx.x >> 5;
    const int lane = threadIdx.x & 31;
    const unsigned lmask = (1u << lane) - 1u;
    const int r0 = wid * 16;
    const float* base = hm + (size_t)plane * HWN + lane*4;

    if (threadIdx.x == 0){ scnt = 0; scnt2 = 0; sCut = 0; }
    for (int i = threadIdx.x; i < NB1; i += 256) shist[i] = 0;
    __syncthreads();

    // ---- NMS: register-rolling separable 3x3 max ----
    float4 v_cur, v_next, h_prev, h_cur, h_next;
    if (r0 > 0){
        h_prev = hmax4(*(const float4*)(base + (size_t)(r0-1)*WN), lane);
    } else {
        h_prev = make_float4(NEG_INF, NEG_INF, NEG_INF, NEG_INF);
    }
    v_cur = *(const float4*)(base + (size_t)r0*WN);
    h_cur = hmax4(v_cur, lane);

    #pragma unroll 3
    for (int r = r0; r < r0 + 15; ++r){
        v_next = *(const float4*)(base + (size_t)(r+1)*WN);
        h_next = hmax4(v_next, lane);
        emit_row(v_cur, h_prev, h_cur, h_next, r, lane, lmask, ch, &scnt, sbuf);
        h_prev = h_cur; h_cur = h_next; v_cur = v_next;
    }
    if (r0 + 16 < HN){
        h_next = hmax4(*(const float4*)(base + (size_t)(r0+16)*WN), lane);
    } else {
        h_next = make_float4(NEG_INF, NEG_INF, NEG_INF, NEG_INF);
    }
    emit_row(v_cur, h_prev, h_cur, h_next, r0+15, lane, lmask, ch, &scnt, sbuf);

    // ---- per-plane histogram -> plane cut ----
    __syncthreads();
    const int nc = (scnt > SBUF) ? SBUF : scnt;
    for (int i = threadIdx.x; i < nc; i += 256){
        float v = __uint_as_float((unsigned)(sbuf[i] >> 32));
        atomicAdd(&shist[bin1f(v)], 1);
    }
    __syncthreads();
    if (wid == 0){
        int cut = cut_scan(shist, 0, lane);
        if (lane == 0) sCut = cut;
    }
    __syncthreads();
    const int p1 = sCut;

    // ---- compact plane survivors (bin >= p1) into shared staging ----
    for (int i0 = 0; i0 < nc; i0 += 256){
        const int i = i0 + threadIdx.x;
        const bool valid = (i < nc);
        unsigned long long kk = valid ? sbuf[i] : 0ull;
        int bin = bin1f(__uint_as_float((unsigned)(kk >> 32)));
        bool take = valid && (bin >= p1);
        unsigned bal = __ballot_sync(FULLM, take);
        int wb = 0;
        if (lane == 0 && bal) wb = atomicAdd(&scnt2, __popc(bal));
        wb = __shfl_sync(FULLM, wb, 0);
        if (take){
            int pos = wb + __popc(bal & lmask);
            if (pos < SCMP) sstage[pos] = kk;
        }
    }
    __syncthreads();
    const int total = (scnt2 > SCMP) ? SCMP : scnt2;
    if (threadIdx.x == 0) sBase = atomicAdd(&g_bcnt[b], total);
    __syncthreads();
    const int gbase = sBase;
    for (int i = threadIdx.x; i < total; i += 256){
        int gp = gbase + i;
        if (gp < BCAP2){
            unsigned long long kk = sstage[i];
            g_bcand[b][gp] = kk;
            // count exactly the items actually present in g_bcand
            float v = __uint_as_float((unsigned)(kk >> 32));
            atomicAdd(&g_hist[b][bin1f(v)], 1);       // REDG, no return
        }
    }
}

// K2: one block per batch; PDL-launched. Reads the K1-built level-1 histogram
// (and resets it), cuts b1, then ONE pass over the contiguous candidates doing
// compaction + level-2 sub-binning, cut b2, refined compact, rank, decode.
__global__ __launch_bounds__(1024) void filter_rank_kernel(const float* __restrict__ offset,
                                                           const float* __restrict__ wh,
                                                           float* __restrict__ out){
    __shared__ int hist[NB1];       // level-1 (from global)
    __shared__ int hist2[NB1];      // level-2
    __shared__ unsigned long long sv[SCAP];
    __shared__ unsigned long long sv2[RCAP];
    __shared__ int sB1, sB2, sCol, sCol2, sCntHi;
    const int b    = blockIdx.x;
    const int tid  = threadIdx.x;
    const int wid  = tid >> 5;
    const int lane = tid & 31;
    const unsigned lmask = (1u << lane) - 1u;

    cudaGridDependencySynchronize();               // PDL: wait for nms completion

    if (tid == 0){ sB1 = 0; sB2 = 0; sCol = 0; sCol2 = 0; sCntHi = 0; }
    for (int i = tid; i < NB1; i += 1024){
        int c = g_hist[b][i];
        hist[i] = c;
        hist2[i] = 0;
        if (c) g_hist[b][i] = 0;                   // consumer reset (write only if dirty)
    }
    int cnt = g_bcnt[b]; if (cnt > BCAP2) cnt = BCAP2;
    const unsigned long long* src = g_bcand[b];
    __syncthreads();
    if (wid == 0){
        int cut = cut_scan(hist, 0, lane);
        if (lane == 0) sB1 = cut;
    }
    __syncthreads();
    const int b1 = sB1;
    // cntHi = number of items strictly above bin b1 (from level-1 hist)
    for (int i = tid; i < NB1; i += 1024)
        if (i > b1 && hist[i]) atomicAdd(&sCntHi, hist[i]);

    // Single pass: compact survivors (bin >= b1) AND build level-2 hist of bin==b1
    for (int i0 = 0; i0 < cnt; i0 += 1024){
        const int i = i0 + tid;
        const bool valid = (i < cnt);
        unsigned long long kk = valid ? src[i] : 0ull;
        float v = __uint_as_float((unsigned)(kk >> 32));
        int bin = bin1f(v);
        bool take = valid && (bin >= b1);
        unsigned bal = __ballot_sync(FULLM, take);
        int wb = 0;
        if (lane == 0 && bal) wb = atomicAdd(&sCol, __popc(bal));
        wb = __shfl_sync(FULLM, wb, 0);
        if (take){
            int pos = wb + __popc(bal & lmask);
            if (pos < SCAP) sv[pos] = kk;
            if (bin == b1) atomicAdd(&hist2[bin2f(v, b1)], 1);
        }
    }
    __syncthreads();
    const int m = (sCol > SCAP) ? SCAP : sCol;
    if (wid == 0){
        int cut = cut_scan(hist2, sCntHi, lane);
        if (lane == 0) sB2 = cut;
    }
    __syncthreads();
    const int b2 = sB2;

    // Compact refined set (~101 items). Ranks within it equal global ranks.
    for (int i0 = 0; i0 < m; i0 += 1024){
        const int i = i0 + tid;
        const bool valid = (i < m);
        unsigned long long kk = valid ? sv[i] : 0ull;
        float v = __uint_as_float((unsigned)(kk >> 32));
        bool take = valid && ((bin1f(v) > b1) || (bin2f(v, b1) >= b2));
        unsigned bal = __ballot_sync(FULLM, take);
        int wb = 0;
        if (lane == 0 && bal) wb = atomicAdd(&sCol2, __popc(bal));
        wb = __shfl_sync(FULLM, wb, 0);
        if (take){
            int pos = wb + __popc(bal & lmask);
            if (pos < RCAP) sv2[pos] = kk;
        }
    }
    __syncthreads();
    const int m2 = (sCol2 > RCAP) ? RCAP : sCol2;

    for (int e = tid; e < m2; e += 1024){
        unsigned long long key = sv2[e];
        int rank = 0;
        for (int j = 0; j < m2; ++j) rank += (sv2[j] > key);
        if (rank < TOPK){
            unsigned vb = (unsigned)(key >> 32);
            int idx = (int)(~(unsigned)key);
            float score = __uint_as_float(vb);
            int chn = idx / HWN;
            int spatial = idx - chn*HWN;
            int ys = spatial >> 7, xs = spatial & (WN-1);
            const float* offb = offset + (size_t)b * 2 * HWN;
            const float* whb  = wh     + (size_t)b * 2 * HWN;
            float ox = offb[spatial], oy = offb[HWN + spatial];
            float ww = whb[spatial],  hh = whb[HWN + spatial];
            float cx = (float)xs + ox, cy = (float)ys + oy;
            float hw2 = ww * 0.5f, hh2 = hh * 0.5f;

            float* out_ids = out;                 // (B,100,1)
            float* out_sc  = out + BN*TOPK;       // (B,100,1)
            float* out_bb  = out + 2*BN*TOPK;     // (B,100,4)
            out_ids[b*TOPK + rank] = (float)chn;
            out_sc [b*TOPK + rank] = score;
            float* bbp = out_bb + (size_t)(b*TOPK + rank)*4;
            bbp[0] = (cx - hw2)*4.0f;
            bbp[1] = (cy - hh2)*4.0f;
            bbp[2] = (cx + hw2)*4.0f;
            bbp[3] = (cy + hh2)*4.0f;
        }
    }

    // consumer reset so the next replay starts from a clean counter
    __syncthreads();
    if (tid == 0) g_bcnt[b] = 0;
}

extern "C" void kernel_launch(void* const* d_in, const int* in_sizes, int n_in,
                              void* d_out, int out_size){
    const float* hm     = (const float*)d_in[0];
    const float* offset = (const float*)d_in[1];
    const float* wh     = (const float*)d_in[2];
    float* out = (float*)d_out;

    nms_kernel<<<NPLANES, 256>>>(hm);

    // PDL launch: K2 setup overlaps K1's tail; data dependency enforced by
    // cudaGridDependencySynchronize() inside the kernel.
    cudaLaunchConfig_t cfg = {};
    cfg.gridDim  = dim3(BN, 1, 1);
    cfg.blockDim = dim3(1024, 1, 1);
    cfg.dynamicSmemBytes = 0;
    cfg.stream = 0;
    cudaLaunchAttribute attr[1];
    attr[0].id = cudaLaunchAttributeProgrammaticStreamSerialization;
    attr[0].val.programmaticStreamSerializationAllowed = 1;
    cfg.attrs = attr;
    cfg.numAttrs = 1;
    cudaLaunchKernelEx(&cfg, filter_rank_kernel, offset, wh, out);
}